// round 11
// baseline (speedup 1.0000x reference)
#include <cuda_runtime.h>
#include <cuda_fp16.h>

// Problem constants (fixed shapes from reference)
#define B_   2
#define T_   32
#define C_   128
#define G_   4
#define CPG  32      // channels per head-group = C/G
#define H_   64
#define W_   64
#define HC_  16      // coarse h
#define WC_  16      // coarse w
#define TQ   16      // q-chunk per block
#define HW_  (H_*W_)     // 4096
#define CHW_ (C_*HW_)    // 524288

typedef unsigned long long u64t;

// out[b,q,g*CPG+c,h,w] = sum_k A_fine[g,b,q,k,h,w] * x[b,k,g*CPG+c,h,w]
// A_fine = bilinear upsample (x4, half-pixel centers, edge clamp) of attn.
// A stored as half2 q-pairs (values in [0,1], 2^-11 quantization), 8 qpairs
// (32 B) contiguous per (k, lane) -> TWO LDS.128 per k; fp32 FFMA2 accum.
// TQ=16: each x scalar feeds 16 q -> warp-k instance count halved vs TQ=8.

__device__ __forceinline__ void ffma2(u64t& d, u64t a, u64t b) {
    asm("fma.rn.f32x2 %0, %1, %2, %0;" : "+l"(d) : "l"(a), "l"(b));
}
__device__ __forceinline__ u64t bcast2(float x) {
    u64t d;
    asm("mov.b64 %0, {%1, %1};" : "=l"(d) : "f"(x));
    return d;
}
__device__ __forceinline__ u64t pack2(float lo, float hi) {
    u64t d;
    asm("mov.b64 %0, {%1, %2};" : "=l"(d) : "f"(lo), "f"(hi));
    return d;
}
__device__ __forceinline__ void unpack2(float& lo, float& hi, u64t v) {
    asm("mov.b64 {%0, %1}, %2;" : "=f"(lo), "=f"(hi) : "l"(v));
}

__global__ __launch_bounds__(512, 2) void temporal_agg_kernel(
    const float* __restrict__ x,
    const float* __restrict__ attn,
    float* __restrict__ out)
{
    __shared__ float Cy[8 * T_ * WC_];                    // one q-half stage  16 KB
    __shared__ __align__(16) __half2 A2h[T_ * 32 * 8];    // [k][wl][qp0..7]   32 KB

    const int qc  = blockIdx.x;          // 0..1  (q-chunk of 16) -- fastest: L2 reuse
    const int wch = blockIdx.y;          // 0..1  (w-chunk of 32)
    const int zz  = blockIdx.z;          // (b*G+g)*H + h
    const int h   = zz & (H_ - 1);
    const int bg  = zz >> 6;
    const int g   = bg & (G_ - 1);
    const int b   = bg >> 2;

    const int tid = threadIdx.x;         // 0..511
    const int wl  = tid & 31;

    // ---- y interpolation coefficients for this fine row h ----
    // src_y = (h + 0.5)/4 - 0.5 = h*0.25 - 0.375 ; edge clamp
    float fy  = h * 0.25f - 0.375f;
    float fyf = floorf(fy);
    float wy1 = fy - fyf;
    int   h0  = (int)fyf;
    int   h1  = min(h0 + 1, HC_ - 1);
    h0 = max(h0, 0);

    // ---- per-lane x-lerp coefficients (used in phase 1b) ----
    const int wf = wch * 32 + wl;
    float fx  = wf * 0.25f - 0.375f;
    float fxf = floorf(fx);
    float wx1 = fx - fxf;
    int   w0  = (int)fxf;
    int   w1  = min(w0 + 1, WC_ - 1);
    w0 = max(w0, 0);

    // ---- phase 1: two q-halves of 8, staged through Cy ----
    // coarse attn layout: ((((g*B+b)*T + q)*T + k)*HC + hc)*WC + wc
    const float* cb0 = attn + ((((size_t)g * B_ + b) * T_ + (size_t)qc * TQ) * T_) * (HC_ * WC_);
    #pragma unroll
    for (int qh = 0; qh < 2; ++qh) {
        // 1a: Cy[(qloc*32+k)][wc] = lerp_y for qloc in [0,8) of this half
        const float* cb = cb0 + (size_t)qh * 8 * T_ * (HC_ * WC_);
        #pragma unroll
        for (int i = 0; i < (8 * T_ * WC_) / 512; ++i) {   // 8 iters
            int idx = i * 512 + tid;
            int wc  = idx & (WC_ - 1);
            int qk  = idx >> 4;              // qloc*32 + k
            const float* p = cb + qk * (HC_ * WC_) + wc;
            float v0 = p[h0 * WC_];
            float v1 = p[h1 * WC_];
            Cy[idx] = fmaf(wy1, v1 - v0, v0);
        }
        __syncthreads();

        // 1b: x-lerp + transpose -> A2h[k][wl][4*qh + j], j=0..3 (q pairs)
        {
            const int kb = tid >> 5;                  // 0..15
            #pragma unroll
            for (int i = 0; i < 2; ++i) {
                int k = kb + 16 * i;                  // 0..31
                float a[8];
                #pragma unroll
                for (int q = 0; q < 8; ++q) {
                    float v0 = Cy[(q * T_ + k) * WC_ + w0];
                    float v1 = Cy[(q * T_ + k) * WC_ + w1];
                    a[q] = fmaf(wx1, v1 - v0, v0);
                }
                __half2 hp[4];
                #pragma unroll
                for (int j = 0; j < 4; ++j)
                    hp[j] = __floats2half2_rn(a[2 * j], a[2 * j + 1]);
                uint2 lohi0 = make_uint2(*(unsigned*)&hp[0], *(unsigned*)&hp[1]);
                uint2 lohi1 = make_uint2(*(unsigned*)&hp[2], *(unsigned*)&hp[3]);
                __half2* dst = &A2h[(k * 32 + wl) * 8 + 4 * qh];
                *(uint2*)(dst)     = lohi0;
                *(uint2*)(dst + 2) = lohi1;
            }
        }
        __syncthreads();
    }

    // ---- phase 2: per-pixel GEMM slice, 8 q-pairs x 2 channels ----
    // thread: w lane (32), channel pair cg (16 warps) -> 2 channels each
    const int cg = tid >> 5;                       // 0..15
    const int cbase = g * CPG + cg * 2;

    const float* xp = x + ((size_t)b * T_ * C_ + cbase) * HW_ + h * W_ + wf;
    const uint4* a4 = (const uint4*)A2h;           // 2 uint4 per (k, wl) slot

    u64t acc[8][2];                                // [qpair][c]
    #pragma unroll
    for (int qp = 0; qp < 8; ++qp) {
        acc[qp][0] = 0ull; acc[qp][1] = 0ull;
    }

    #pragma unroll 4
    for (int k = 0; k < T_; ++k) {
        const float* xk = xp + k * CHW_;           // 32-bit offset arithmetic
        u64t xv0 = bcast2(xk[0]);
        u64t xv1 = bcast2(xk[HW_]);
        uint4 araw0 = a4[2 * (k * 32 + wl)];       // qpairs 0..3 (16 B)
        uint4 araw1 = a4[2 * (k * 32 + wl) + 1];   // qpairs 4..7 (16 B)
        const __half2* ah0 = (const __half2*)&araw0;
        const __half2* ah1 = (const __half2*)&araw1;
        #pragma unroll
        for (int j = 0; j < 4; ++j) {
            float2 f = __half22float2(ah0[j]);
            u64t av = pack2(f.x, f.y);
            ffma2(acc[j][0], av, xv0);
            ffma2(acc[j][1], av, xv1);
        }
        #pragma unroll
        for (int j = 0; j < 4; ++j) {
            float2 f = __half22float2(ah1[j]);
            u64t av = pack2(f.x, f.y);
            ffma2(acc[4 + j][0], av, xv0);
            ffma2(acc[4 + j][1], av, xv1);
        }
    }

    // ---- store: out[(((b*T+q)*C + c)*H + h)*W + w], q = 2*qp + {0,1} ----
    float* ob = out + (((size_t)b * T_ + (size_t)qc * TQ) * C_ + cbase) * HW_ + h * W_ + wf;
    #pragma unroll
    for (int qp = 0; qp < 8; ++qp) {
        #pragma unroll
        for (int c = 0; c < 2; ++c) {
            float lo, hi;
            unpack2(lo, hi, acc[qp][c]);
            ob[(2 * qp) * CHW_ + c * HW_]     = lo;
            ob[(2 * qp + 1) * CHW_ + c * HW_] = hi;
        }
    }
}

extern "C" void kernel_launch(void* const* d_in, const int* in_sizes, int n_in,
                              void* d_out, int out_size)
{
    const float* x    = (const float*)d_in[0];   // (2,32,128,64,64)
    const float* attn = (const float*)d_in[1];   // (4,2,32,32,16,16)
    float* out        = (float*)d_out;           // (2,32,128,64,64)

    dim3 grid(T_ / TQ /*2 q-chunks*/, W_ / 32 /*2 w-chunks*/, B_ * G_ * H_ /*512*/);
    temporal_agg_kernel<<<grid, 512>>>(x, attn, out);
}

// round 12
// speedup vs baseline: 1.1134x; 1.1134x over previous
#include <cuda_runtime.h>
#include <cuda_fp16.h>

// Problem constants (fixed shapes from reference)
#define B_   2
#define T_   32
#define C_   128
#define G_   4
#define CPG  32      // channels per head-group = C/G
#define H_   64
#define W_   64
#define HC_  16      // coarse h
#define WC_  16      // coarse w
#define TQ   8       // q-chunk per block
#define HW_  (H_*W_)     // 4096
#define CHW_ (C_*HW_)    // 524288

typedef unsigned long long u64t;

// out[b,q,g*CPG+c,h,w] = sum_k A_fine[g,b,q,k,h,w] * x[b,k,g*CPG+c,h,w]
// A_fine = bilinear upsample (x4, half-pixel centers, edge clamp) of attn.
// Champion mainloop (R9): q8c4 per thread, A as half2 q-pairs (LDS.32,
// 4B lane stride conflict-free), fp32 FFMA2 accumulation.
// This round: one 512-thread block covers all 64 w -> phase-1a coarse-attn
// loads and Cy staging amortized over both w-halves (was duplicated).

__device__ __forceinline__ void ffma2(u64t& d, u64t a, u64t b) {
    asm("fma.rn.f32x2 %0, %1, %2, %0;" : "+l"(d) : "l"(a), "l"(b));
}
__device__ __forceinline__ u64t bcast2(float x) {
    u64t d;
    asm("mov.b64 %0, {%1, %1};" : "=l"(d) : "f"(x));
    return d;
}
__device__ __forceinline__ u64t pack2(float lo, float hi) {
    u64t d;
    asm("mov.b64 %0, {%1, %2};" : "=l"(d) : "f"(lo), "f"(hi));
    return d;
}
__device__ __forceinline__ void unpack2(float& lo, float& hi, u64t v) {
    asm("mov.b64 {%0, %1}, %2;" : "=f"(lo), "=f"(hi) : "l"(v));
}

__global__ __launch_bounds__(512, 2) void temporal_agg_kernel(
    const float* __restrict__ x,
    const float* __restrict__ attn,
    float* __restrict__ out)
{
    __shared__ float   Cy[TQ * T_ * WC_];          // [q*32+k][wc]        16 KB
    __shared__ __half2 A2h[T_ * 4 * W_];           // [k][qpair][w64]     32 KB

    const int qc  = blockIdx.x;          // 0..3  (q-chunk)  -- fastest: L2 reuse of x
    const int zz  = blockIdx.y;          // (b*G+g)*H + h
    const int h   = zz & (H_ - 1);
    const int bg  = zz >> 6;
    const int g   = bg & (G_ - 1);
    const int b   = bg >> 2;

    const int tid  = threadIdx.x;        // 0..511
    const int wl   = tid & 31;
    const int warp = tid >> 5;           // 0..15

    // ---- y interpolation coefficients for this fine row h ----
    // src_y = (h + 0.5)/4 - 0.5 = h*0.25 - 0.375 ; edge clamp
    float fy  = h * 0.25f - 0.375f;
    float fyf = floorf(fy);
    float wy1 = fy - fyf;
    int   h0  = (int)fyf;
    int   h1  = min(h0 + 1, HC_ - 1);
    h0 = max(h0, 0);

    // ---- phase 1a: Cy[q*32+k][wc] = lerp_y(coarse), once for both w-halves ----
    // coarse attn layout: ((((g*B+b)*T + q)*T + k)*HC + hc)*WC + wc
    const float* cb = attn + ((((size_t)g * B_ + b) * T_ + (size_t)qc * TQ) * T_) * (HC_ * WC_);
    #pragma unroll
    for (int i = 0; i < (TQ * T_ * WC_) / 512; ++i) {    // 8 iters
        int idx = i * 512 + tid;
        int wc  = idx & (WC_ - 1);
        int qk  = idx >> 4;               // q*32 + k
        const float* p = cb + qk * (HC_ * WC_) + wc;
        float v0 = p[h0 * WC_];
        float v1 = p[h1 * WC_];
        Cy[idx] = fmaf(wy1, v1 - v0, v0);
    }
    __syncthreads();

    // ---- phase 1b: x-lerp + transpose -> A2h[k][qp][wf] (half2 q-pairs) ----
    // warp -> (k-slice kh = warp>>1, w-half wh = warp&1); thread covers wf.
    {
        const int wh  = warp & 1;
        const int kh  = warp >> 1;                // 0..7
        const int wf  = wh * 32 + wl;
        float fx  = wf * 0.25f - 0.375f;
        float fxf = floorf(fx);
        float wx1 = fx - fxf;
        int   w0  = (int)fxf;
        int   w1  = min(w0 + 1, WC_ - 1);
        w0 = max(w0, 0);
        #pragma unroll
        for (int i = 0; i < 4; ++i) {
            int k = kh + 8 * i;                   // 0..31
            float a[TQ];
            #pragma unroll
            for (int q = 0; q < TQ; ++q) {
                float v0 = Cy[(q * T_ + k) * WC_ + w0];
                float v1 = Cy[(q * T_ + k) * WC_ + w1];
                a[q] = fmaf(wx1, v1 - v0, v0);
            }
            #pragma unroll
            for (int qp = 0; qp < 4; ++qp)
                A2h[(k * 4 + qp) * W_ + wf] =
                    __floats2half2_rn(a[2 * qp], a[2 * qp + 1]);
        }
    }
    __syncthreads();

    // ---- phase 2: per-pixel GEMM slice, f32x2 over q-pairs (champion loop) ----
    // warp -> (w-half = warp>>3, channel group cg = warp&7) -> 4 channels each
    const int wchm = warp >> 3;
    const int cg   = warp & 7;
    const int wf   = wchm * 32 + wl;
    const int cbase = g * CPG + cg * 4;

    const float* xp = x + ((size_t)b * T_ * C_ + cbase) * HW_ + h * W_ + wf;
    const __half2* ahp = A2h + wf;

    u64t acc[4][4];                     // [qpair][c]
    #pragma unroll
    for (int qp = 0; qp < 4; ++qp)
        #pragma unroll
        for (int c = 0; c < 4; ++c)
            acc[qp][c] = 0ull;

    #pragma unroll 4
    for (int k = 0; k < T_; ++k) {
        const float* xk = xp + k * CHW_;          // 32-bit offset arithmetic
        u64t xv[4];
        #pragma unroll
        for (int c = 0; c < 4; ++c)
            xv[c] = bcast2(xk[c * HW_]);
        u64t av[4];
        #pragma unroll
        for (int qp = 0; qp < 4; ++qp) {
            float2 f = __half22float2(ahp[(k * 4 + qp) * W_]);
            av[qp] = pack2(f.x, f.y);
        }
        #pragma unroll
        for (int qp = 0; qp < 4; ++qp)
            #pragma unroll
            for (int c = 0; c < 4; ++c)
                ffma2(acc[qp][c], av[qp], xv[c]);
    }

    // ---- store: out[(((b*T+q)*C + c)*H + h)*W + w] ----
    float* ob = out + (((size_t)b * T_ + (size_t)qc * TQ) * C_ + cbase) * HW_ + h * W_ + wf;
    #pragma unroll
    for (int qp = 0; qp < 4; ++qp) {
        #pragma unroll
        for (int c = 0; c < 4; ++c) {
            float lo, hi;
            unpack2(lo, hi, acc[qp][c]);
            ob[(2 * qp) * CHW_ + c * HW_]     = lo;
            ob[(2 * qp + 1) * CHW_ + c * HW_] = hi;
        }
    }
}

extern "C" void kernel_launch(void* const* d_in, const int* in_sizes, int n_in,
                              void* d_out, int out_size)
{
    const float* x    = (const float*)d_in[0];   // (2,32,128,64,64)
    const float* attn = (const float*)d_in[1];   // (4,2,32,32,16,16)
    float* out        = (float*)d_out;           // (2,32,128,64,64)

    dim3 grid(T_ / TQ /*4 q-chunks*/, B_ * G_ * H_ /*512*/);
    temporal_agg_kernel<<<grid, 512>>>(x, attn, out);
}